// round 3
// baseline (speedup 1.0000x reference)
#include <cuda_runtime.h>
#include <cstdint>

typedef unsigned long long u64;

#define BB 4
#define CC 64
#define HH 256
#define WW 512
#define HWW (HH*WW)
#define KTOT 576            // 9 taps * 64 ci
#define STR  580            // padded row stride (floats): conflict-free + 16B aligned
#define NPIX 32             // pixels per tile
#define NTHREADS 512
#define TILES_PER_ROW (WW/NPIX)       // 16
#define NTILES (BB*HH*TILES_PER_ROW)  // 16384
#define SMEM_BYTES ((CC+NPIX)*STR*4)  // 222720 B
#define GRID_MAIN 148
#define IDX_N (3*HH*3*WW)             // 1179648 logical indices

// scratch (no runtime allocation allowed)
__device__ float g_xt[(size_t)BB*HWW*CC];   // x transposed to [b][hw][c]
__device__ float g_wt[CC*KTOT];             // weight reordered to [co][p*64+ci]
__device__ int   g_is64;                    // 1 if idx buffer is int64, 0 if int32

// ---------------------------------------------------------------------------
// x[b][c][hw] -> g_xt[b][hw][c]  (coalesced both sides via 32x32 smem tile)
// ---------------------------------------------------------------------------
__global__ void transpose_kernel(const float* __restrict__ x){
    __shared__ float tile[32][33];
    int b  = blockIdx.z;
    int s0 = blockIdx.x * 32;
    int c0 = blockIdx.y * 32;
    const float* xb = x + (size_t)b*CC*HWW;
    #pragma unroll
    for (int i = threadIdx.y; i < 32; i += 8)
        tile[i][threadIdx.x] = xb[(size_t)(c0+i)*HWW + s0 + threadIdx.x];
    __syncthreads();
    float* xtb = g_xt + (size_t)b*HWW*CC;
    #pragma unroll
    for (int i = threadIdx.y; i < 32; i += 8)
        xtb[(size_t)(s0+i)*CC + c0 + threadIdx.x] = tile[threadIdx.x][i];
}

// ---------------------------------------------------------------------------
// weight[co][ci][ky][kx] -> g_wt[co][k], k = (ky*3+kx)*64 + ci.
// Block 0 / thread 0 also resets the dtype flag (runs before the probe).
// ---------------------------------------------------------------------------
__global__ void wprep_kernel(const float* __restrict__ w){
    if (blockIdx.x == 0 && threadIdx.x == 0) g_is64 = 1;
    int i = blockIdx.x*256 + threadIdx.x;
    if (i < CC*KTOT){
        int co = i / KTOT;
        int k  = i - co*KTOT;
        int p  = k >> 6;     // tap 0..8
        int ci = k & 63;
        g_wt[i] = w[(co*CC + ci)*9 + p];
    }
}

// ---------------------------------------------------------------------------
// dtype probe: view idx buffer as int64 and scan the first IDX_N/2 elements
// (safe under both interpretations: buffer holds at least IDX_N*4 bytes).
// Any value outside [0, HWW) => the buffer is actually int32.
// ---------------------------------------------------------------------------
__global__ void idx_probe_kernel(const long long* __restrict__ idx64){
    long long bad = 0;
    for (int i = blockIdx.x*blockDim.x + threadIdx.x; i < IDX_N/2;
         i += gridDim.x*blockDim.x){
        long long v = idx64[i];
        if (v < 0 || v >= HWW) bad = 1;
    }
    if (__syncthreads_or(bad != 0) && threadIdx.x == 0)
        g_is64 = 0;
}

// ---------------------------------------------------------------------------
// Persistent main kernel: weight in smem (64x580), per tile gather 32 pixels
// x 9 taps x 64 ci into smem (32x580), then register-tiled f32x2 GEMM.
// ---------------------------------------------------------------------------
__global__ void __launch_bounds__(NTHREADS, 1)
latconv_main(const void* __restrict__ idx_raw,
             const float* __restrict__ bias,
             float* __restrict__ out)
{
    extern __shared__ float sm[];
    float* Ws = sm;                    // CC x STR
    float* Vs = sm + CC*STR;           // NPIX x STR

    const int tid = threadIdx.x;
    const int is64 = g_is64;
    const long long* __restrict__ idx64 = (const long long*)idx_raw;
    const int*       __restrict__ idx32 = (const int*)idx_raw;

    for (int i = tid; i < CC*KTOT; i += NTHREADS){
        int co = i / KTOT;
        int k  = i - co*KTOT;
        Ws[co*STR + k] = g_wt[i];
    }

    const int co = tid & 63;
    const int pg = tid >> 6;           // 0..7 -> pixels pg*4 .. pg*4+3
    const float bco = __ldg(&bias[co]);

    const int lane16 = tid & 15;
    const int pair0  = tid >> 4;       // 0..31

    __syncthreads();

    for (int t = blockIdx.x; t < NTILES; t += GRID_MAIN){
        const int w0 = (t & (TILES_PER_ROW-1)) * NPIX;
        const int h  = (t / TILES_PER_ROW) & (HH-1);
        const int b  =  t / (TILES_PER_ROW*HH);
        const float* __restrict__ xtb = g_xt + (size_t)b*HWW*CC;

        // ---- gather: 288 (pixel, tap) pairs, 16 lanes of float4 each ----
        #pragma unroll
        for (int pp = 0; pp < 9; pp++){
            int pair = pair0 + pp*32;          // 0..287
            int pix  = pair / 9;               // 0..31
            int p    = pair - pix*9;           // 0..8
            int dy   = p / 3;
            int dx   = p - dy*3;
            int flat = (3*h + dy)*(3*WW) + 3*(w0 + pix) + dx;
            long long g = is64 ? __ldg(&idx64[flat]) : (long long)__ldg(&idx32[flat]);
            const float4 v = *(const float4*)&xtb[(size_t)g*CC + (lane16<<2)];
            *(float4*)&Vs[pix*STR + (p<<6) + (lane16<<2)] = v;
        }
        __syncthreads();

        // ---- GEMM: out[co][pix] = sum_k Ws[co][k] * Vs[pix][k] ----
        u64 accL[4] = {0ull,0ull,0ull,0ull};
        u64 accH[4] = {0ull,0ull,0ull,0ull};
        const float* __restrict__ wrow = Ws + co*STR;
        const float* __restrict__ vrow = Vs + (pg*4)*STR;

        #pragma unroll 4
        for (int k = 0; k < KTOT; k += 4){
            const ulonglong2 wp = *(const ulonglong2*)(wrow + k);
            #pragma unroll
            for (int i = 0; i < 4; i++){
                const ulonglong2 vp = *(const ulonglong2*)(vrow + i*STR + k);
                asm("fma.rn.f32x2 %0, %1, %2, %0;" : "+l"(accL[i]) : "l"(vp.x), "l"(wp.x));
                asm("fma.rn.f32x2 %0, %1, %2, %0;" : "+l"(accH[i]) : "l"(vp.y), "l"(wp.y));
            }
        }

        // ---- epilogue ----
        float rr[4];
        #pragma unroll
        for (int i = 0; i < 4; i++){
            float l0, l1, h0, h1;
            asm("mov.b64 {%0,%1}, %2;" : "=f"(l0), "=f"(l1) : "l"(accL[i]));
            asm("mov.b64 {%0,%1}, %2;" : "=f"(h0), "=f"(h1) : "l"(accH[i]));
            rr[i] = (l0 + l1) + (h0 + h1) + bco;
        }
        size_t o = (((size_t)b*CC + co)*HH + h)*WW + w0 + pg*4;
        float4 r4; r4.x = rr[0]; r4.y = rr[1]; r4.z = rr[2]; r4.w = rr[3];
        *(float4*)&out[o] = r4;

        __syncthreads();   // protect Vs before next tile's gather
    }
}

// ---------------------------------------------------------------------------
extern "C" void kernel_launch(void* const* d_in, const int* in_sizes, int n_in,
                              void* d_out, int out_size)
{
    const float* x    = (const float*)d_in[0];
    const void*  idx  = d_in[1];
    const float* w    = (const float*)d_in[2];
    const float* bias = (const float*)d_in[3];
    float*       out  = (float*)d_out;

    dim3 tgrid(HWW/32, CC/32, BB);
    transpose_kernel<<<tgrid, dim3(32,8)>>>(x);
    wprep_kernel<<<(CC*KTOT + 255)/256, 256>>>(w);
    idx_probe_kernel<<<148, 256>>>((const long long*)idx);

    cudaFuncSetAttribute(latconv_main,
                         cudaFuncAttributeMaxDynamicSharedMemorySize, SMEM_BYTES);
    latconv_main<<<GRID_MAIN, NTHREADS, SMEM_BYTES>>>(idx, bias, out);
}

// round 5
// speedup vs baseline: 3.5204x; 3.5204x over previous
#include <cuda_runtime.h>
#include <cstdint>

typedef unsigned int u32;
typedef unsigned long long u64;

#define BB 4
#define CC 64
#define HH 256
#define WW 512
#define HWW (HH*WW)
#define NTHREADS 512
#define GRID_MAIN 148
#define NTILES (BB*HH*4)          // tile = 128 consecutive w pixels
#define IDX_N (3*HH*3*WW)

// ---- weight smem image: [plane][co][1168B row], row = tap*128 + ci*2 bytes
#define WROW   1168
#define WPLANE (64*WROW)          // 74752
#define W_BYTES (2*WPLANE)        // 149504

// ---- A tiles: 2 bufs x 2 planes x 128 px x 144B (128B data + 16B pad)
#define AROW   144
#define APLANE (128*AROW)         // 18432
#define ABUF   (2*APLANE)         // 36864
#define SM_W   0
#define SM_A   W_BYTES            // 149504
#define SM_BIAS (SM_A + 2*ABUF)   // 223232
#define SMEM_TOTAL (SM_BIAS + 256)

// ---- global scratch ----
__device__ u32   g_xh[(size_t)BB*HWW*(CC/2)];   // bf16-hi plane [b][hw][ci-pairs] 128B rows
__device__ u32   g_xl[(size_t)BB*HWW*(CC/2)];   // bf16-lo residual plane
__device__ uint4 g_wimg4[W_BYTES/16];           // weight image (hi plane | lo plane)
__device__ int   g_is64;

// =================== helpers ===================
__device__ __forceinline__ u32 smem_u32(const void* p){
    u32 a; asm("{ .reg .u64 t; cvta.to.shared.u64 t, %1; cvt.u32.u64 %0, t; }":"=r"(a):"l"(p));
    return a;
}
__device__ __forceinline__ u32 cvt_bf16x2(float lo, float hi){
    u32 r; asm("cvt.rn.bf16x2.f32 %0, %1, %2;":"=r"(r):"f"(hi),"f"(lo)); return r;
}

#define LDSM4(r, addr) \
    asm volatile("ldmatrix.sync.aligned.m8n8.x4.shared.b16 {%0,%1,%2,%3}, [%4];" \
        : "=r"((r)[0]),"=r"((r)[1]),"=r"((r)[2]),"=r"((r)[3]) : "r"(addr))

#define MMA_BF16(d, a, b0, b1) \
    asm volatile("mma.sync.aligned.m16n8k16.row.col.f32.bf16.bf16.f32 " \
        "{%0,%1,%2,%3},{%4,%5,%6,%7},{%8,%9},{%0,%1,%2,%3};" \
        : "+f"((d)[0]),"+f"((d)[1]),"+f"((d)[2]),"+f"((d)[3]) \
        : "r"((a)[0]),"r"((a)[1]),"r"((a)[2]),"r"((a)[3]), "r"(b0),"r"(b1))

// =================== prepass: transpose + bf16 hi/lo split ===================
__global__ void xprep_kernel(const float* __restrict__ x){
    __shared__ float tile[CC][33];
    int b  = blockIdx.y;
    int s0 = blockIdx.x * 32;
    int tx = threadIdx.x, ty = threadIdx.y;     // 32 x 8
    const float* xb = x + (size_t)b*CC*HWW;
    #pragma unroll
    for (int cc = ty; cc < CC; cc += 8)
        tile[cc][tx] = xb[(size_t)cc*HWW + s0 + tx];
    __syncthreads();
    int part = ty >> 2;                          // 0 = hi plane, 1 = lo plane
    u32* plane = part ? g_xl : g_xh;
    #pragma unroll
    for (int i = (ty & 3); i < 32; i += 4){
        float v0 = tile[2*tx][i], v1 = tile[2*tx+1][i];
        u32 hp = cvt_bf16x2(v0, v1);
        u32 outw = hp;
        if (part){
            float f0 = __uint_as_float(hp << 16);
            float f1 = __uint_as_float(hp & 0xFFFF0000u);
            outw = cvt_bf16x2(v0 - f0, v1 - f1);
        }
        plane[((size_t)b*HWW + s0 + i)*32 + tx] = outw;
    }
}

// =================== weight prep: bf16 hi/lo split, padded-row image ===================
__global__ void wprep_kernel(const float* __restrict__ w){
    if (blockIdx.x == 0 && threadIdx.x == 0) g_is64 = 1;
    int i = blockIdx.x*256 + threadIdx.x;        // 64 co * 288 ci-pairs
    if (i < CC*288){
        int co = i / 288;
        int kp = i - co*288;
        int k  = kp*2;
        int tap = k >> 6, ci = k & 63;
        float v0 = w[(co*CC + ci  )*9 + tap];
        float v1 = w[(co*CC + ci+1)*9 + tap];
        u32 hp = cvt_bf16x2(v0, v1);
        float f0 = __uint_as_float(hp << 16);
        float f1 = __uint_as_float(hp & 0xFFFF0000u);
        u32 lp = cvt_bf16x2(v0 - f0, v1 - f1);
        u32 off = co*WROW + tap*128 + ci*2;      // ci even -> 4B aligned
        char* img = (char*)g_wimg4;
        *(u32*)(img + off)          = hp;
        *(u32*)(img + WPLANE + off) = lp;
    }
}

// =================== idx dtype probe (proven: idx is int32) ===================
__global__ void idx_probe_kernel(const long long* __restrict__ idx64){
    long long bad = 0;
    for (int i = blockIdx.x*blockDim.x + threadIdx.x; i < IDX_N/2;
         i += gridDim.x*blockDim.x){
        long long v = idx64[i];
        if (v < 0 || v >= HWW) bad = 1;
    }
    if (__syncthreads_or(bad != 0) && threadIdx.x == 0) g_is64 = 0;
}

// =================== main: persistent HMMA tile GEMM ===================
// Tile: 128 px x 64 co x (9 taps x 64 ci), bf16 3-product split, f32 accum.
// 16 warps gather; warps 0..7 run mma (warp tile 32 px x 32 co).
__global__ void __launch_bounds__(NTHREADS, 1)
latconv_main(const void* __restrict__ idx_raw,
             const float* __restrict__ bias,
             float* __restrict__ out)
{
    extern __shared__ char sm[];
    const u32 smb = smem_u32(sm);
    const int tid  = threadIdx.x;
    const int wid  = tid >> 5;
    const int lane = tid & 31;

    // weights image -> smem
    {
        uint4* dst = (uint4*)sm;
        for (int i = tid; i < W_BYTES/16; i += NTHREADS) dst[i] = g_wimg4[i];
    }
    if (tid < CC) ((float*)(sm + SM_BIAS))[tid] = bias[tid];
    __syncthreads();

    const int is64 = g_is64;
    const long long* __restrict__ idx64 = (const long long*)idx_raw;
    const int*       __restrict__ idx32 = (const int*)idx_raw;

    // gather mapping: thread -> (pixel, 32B quarter)
    const int px = tid >> 2;
    const int q  = tid & 3;
    const uint4* __restrict__ xh4 = (const uint4*)g_xh;
    const uint4* __restrict__ xl4 = (const uint4*)g_xl;

    // mma mapping
    const bool gemm = (wid < 8);
    const int wm = wid >> 1;           // px strip 32*wm
    const int wn = wid & 1;            // co half 32*wn
    const u32 a_row  = (u32)(wm*32 + (lane & 15));
    const u32 a_koff = (u32)((lane >> 4) * 16);
    const u32 b_co   = (u32)(wn*32 + (lane & 7) + ((lane >> 4) & 1) * 8);
    const u32 b_koff = (u32)(((lane >> 3) & 1) * 16);
    // base addresses (add buf/plane/tile offsets per use)
    const u32 Abase = smb + SM_A + a_row*AROW + a_koff;
    const u32 Bbase = smb + SM_W + b_co*WROW + b_koff;

    const int r     = lane >> 2;       // d-frag row within m16
    const int cpair = (lane & 3) * 2;  // d-frag col pair within n8

    for (int T = blockIdx.x; T < NTILES; T += GRID_MAIN){
        const int wq = T & 3;
        const int h  = (T >> 2) & (HH-1);
        const int b  = T >> 10;
        const int w0 = wq * 128;
        const size_t brow = (size_t)b * HWW;

        float acc[2][4][4];
        #pragma unroll
        for (int i = 0; i < 2; i++)
            #pragma unroll
            for (int j = 0; j < 4; j++)
                #pragma unroll
                for (int kk = 0; kk < 4; kk++) acc[i][j][kk] = 0.f;

        // ---- prologue gather: tap 0 -> buf 0 ----
        {
            const int flat = (3*h + 0)*(3*WW) + 3*(w0 + px) + 0;
            const long long g = is64 ? __ldg(&idx64[flat]) : (long long)__ldg(&idx32[flat]);
            const size_t gu = (brow + (size_t)g)*8 + q*2;
            uint4 h0 = xh4[gu], h1 = xh4[gu+1], l0 = xl4[gu], l1 = xl4[gu+1];
            char* ab = sm + SM_A;                      // buf 0
            const int o = px*AROW + q*32;
            *(uint4*)(ab + o)              = h0;
            *(uint4*)(ab + o + 16)         = h1;
            *(uint4*)(ab + APLANE + o)     = l0;
            *(uint4*)(ab + APLANE + o + 16)= l1;
        }
        __syncthreads();

        for (int p = 0; p < 9; p++){
            const int buf = p & 1;

            // prefetch next tap into regs (latency hidden by mma below)
            uint4 h0, h1, l0, l1;
            if (p < 8){
                const int pn = p + 1;
                const int dy = pn / 3, dx = pn - dy*3;
                const int flat = (3*h + dy)*(3*WW) + 3*(w0 + px) + dx;
                const long long g = is64 ? __ldg(&idx64[flat]) : (long long)__ldg(&idx32[flat]);
                const size_t gu = (brow + (size_t)g)*8 + q*2;
                h0 = xh4[gu]; h1 = xh4[gu+1]; l0 = xl4[gu]; l1 = xl4[gu+1];
            }

            if (gemm){
                const u32 Ah = Abase + buf*ABUF;       // hi plane
                const u32 Al = Ah + APLANE;            // lo plane
                const u32 Bh = Bbase + p*128;          // hi plane
                const u32 Bl = Bh + WPLANE;            // lo plane
                #pragma unroll
                for (int s = 0; s < 4; s++){
                    u32 ah[2][4], al[2][4], bh[2][4], bl[2][4];
                    #pragma unroll
                    for (int mt = 0; mt < 2; mt++){
                        LDSM4(ah[mt], Ah + (mt*16)*AROW + s*32);
                        LDSM4(al[mt], Al + (mt*16)*AROW + s*32);
                    }
                    #pragma unroll
                    for (int g2 = 0; g2 < 2; g2++){
                        LDSM4(bh[g2], Bh + (g2*16)*WROW + s*32);
                        LDSM4(bl[g2], Bl + (g2*16)*WROW + s*32);
                    }
                    #pragma unroll
                    for (int mt = 0; mt < 2; mt++)
                        #pragma unroll
                        for (int g2 = 0; g2 < 2; g2++){
                            MMA_BF16(acc[mt][2*g2  ], ah[mt], bh[g2][0], bh[g2][1]);
                            MMA_BF16(acc[mt][2*g2+1], ah[mt], bh[g2][2], bh[g2][3]);
                            MMA_BF16(acc[mt][2*g2  ], al[mt], bh[g2][0], bh[g2][1]);
                            MMA_BF16(acc[mt][2*g2+1], al[mt], bh[g2][2], bh[g2][3]);
                            MMA_BF16(acc[mt][2*g2  ], ah[mt], bl[g2][0], bl[g2][1]);
                            MMA_BF16(acc[mt][2*g2+1], ah[mt], bl[g2][2], bl[g2][3]);
                        }
                }
            }

            if (p < 8){
                char* ab = sm + SM_A + ((p+1)&1)*ABUF;
                const int o = px*AROW + q*32;
                *(uint4*)(ab + o)              = h0;
                *(uint4*)(ab + o + 16)         = h1;
                *(uint4*)(ab + APLANE + o)     = l0;
                *(uint4*)(ab + APLANE + o + 16)= l1;
            }
            __syncthreads();
        }

        // ---- epilogue: D + bias -> out (NCHW) ----
        if (gemm){
            float* ob = out + (size_t)b*CC*HWW + (size_t)h*WW + w0;
            const float* bs = (const float*)(sm + SM_BIAS);
            #pragma unroll
            for (int mt = 0; mt < 2; mt++){
                const int px0 = wm*32 + mt*16 + r;
                #pragma unroll
                for (int nt = 0; nt < 4; nt++){
                    const int co = wn*32 + nt*8 + cpair;
                    const float b0 = bs[co], b1 = bs[co+1];
                    ob[(size_t)co*HWW     + px0    ] = acc[mt][nt][0] + b0;
                    ob[(size_t)(co+1)*HWW + px0    ] = acc[mt][nt][1] + b1;
                    ob[(size_t)co*HWW     + px0 + 8] = acc[mt][nt][2] + b0;
                    ob[(size_t)(co+1)*HWW + px0 + 8] = acc[mt][nt][3] + b1;
                }
            }
        }
        // next tile's prologue gather writes buf0, which mma finished reading
        // before the last __syncthreads above -- safe.
    }
}

// =================== launch ===================
extern "C" void kernel_launch(void* const* d_in, const int* in_sizes, int n_in,
                              void* d_out, int out_size)
{
    const float* x    = (const float*)d_in[0];
    const void*  idx  = d_in[1];
    const float* w    = (const float*)d_in[2];
    const float* bias = (const float*)d_in[3];
    float*       out  = (float*)d_out;

    xprep_kernel<<<dim3(HWW/32, BB), dim3(32,8)>>>(x);
    wprep_kernel<<<(CC*288 + 255)/256, 256>>>(w);
    idx_probe_kernel<<<148, 256>>>((const long long*)idx);

    cudaFuncSetAttribute(latconv_main,
                         cudaFuncAttributeMaxDynamicSharedMemorySize, SMEM_TOTAL);
    latconv_main<<<GRID_MAIN, NTHREADS, SMEM_TOTAL>>>(idx, bias, out);
}

// round 7
// speedup vs baseline: 3.8706x; 1.0995x over previous
#include <cuda_runtime.h>
#include <cstdint>

typedef unsigned int u32;

#define BB 4
#define CC 64
#define HH 256
#define WW 512
#define HWW (HH*WW)
#define GRID_MAIN 148
#define NTILES (BB*HH*4)          // tile = 128 consecutive w pixels
#define IDX_N (3*HH*3*WW)
#define NT 256                    // 8 warps: 2 tile-groups x 4 warps

// ---- weight smem image: [plane][co][1168B row], row = tap*128 + ci*2 bytes
#define WROW   1168
#define WPLANE (64*WROW)          // 74752
#define W_BYTES (2*WPLANE)        // 149504
#define SM_BIAS W_BYTES
#define SMEM_TOTAL (W_BYTES + 256)

// ---- global scratch ----
__device__ u32   g_xh[(size_t)BB*HWW*32];   // bf16-hi plane [b][hw][ci-pair words]
__device__ u32   g_xl[(size_t)BB*HWW*32];   // bf16-lo residual plane
__device__ uint4 g_wimg4[W_BYTES/16];       // weight image (hi plane | lo plane)
__device__ int   g_idx[IDX_N];              // canonical int32 indices
__device__ int   g_is64;

// =================== helpers ===================
__device__ __forceinline__ u32 smem_u32(const void* p){
    u32 a; asm("{ .reg .u64 t; cvta.to.shared.u64 t, %1; cvt.u32.u64 %0, t; }":"=r"(a):"l"(p));
    return a;
}
__device__ __forceinline__ u32 cvt_bf16x2(float lo, float hi){
    u32 r; asm("cvt.rn.bf16x2.f32 %0, %1, %2;":"=r"(r):"f"(hi),"f"(lo)); return r;
}

#define LDSM4(r, addr) \
    asm volatile("ldmatrix.sync.aligned.m8n8.x4.shared.b16 {%0,%1,%2,%3}, [%4];" \
        : "=r"((r)[0]),"=r"((r)[1]),"=r"((r)[2]),"=r"((r)[3]) : "r"(addr))

#define MMA_BF16(d, a, b0, b1) \
    asm volatile("mma.sync.aligned.m16n8k16.row.col.f32.bf16.bf16.f32 " \
        "{%0,%1,%2,%3},{%4,%5,%6,%7},{%8,%9},{%0,%1,%2,%3};" \
        : "+f"((d)[0]),"+f"((d)[1]),"+f"((d)[2]),"+f"((d)[3]) \
        : "r"((a)[0]),"r"((a)[1]),"r"((a)[2]),"r"((a)[3]), "r"(b0),"r"(b1))

// =================== prepass: transpose + bf16 hi/lo split ===================
__global__ void xprep_kernel(const float* __restrict__ x){
    __shared__ float tile[CC][33];
    int b  = blockIdx.y;
    int s0 = blockIdx.x * 32;
    int tx = threadIdx.x, ty = threadIdx.y;     // 32 x 8
    const float* xb = x + (size_t)b*CC*HWW;
    #pragma unroll
    for (int cc = ty; cc < CC; cc += 8)
        tile[cc][tx] = xb[(size_t)cc*HWW + s0 + tx];
    __syncthreads();
    int part = ty >> 2;                          // 0 = hi plane, 1 = lo plane
    u32* plane = part ? g_xl : g_xh;
    #pragma unroll
    for (int i = (ty & 3); i < 32; i += 4){
        float v0 = tile[2*tx][i], v1 = tile[2*tx+1][i];
        u32 hp = cvt_bf16x2(v0, v1);
        u32 outw = hp;
        if (part){
            float f0 = __uint_as_float(hp << 16);
            float f1 = __uint_as_float(hp & 0xFFFF0000u);
            outw = cvt_bf16x2(v0 - f0, v1 - f1);
        }
        plane[((size_t)b*HWW + s0 + i)*32 + tx] = outw;
    }
}

// =================== weight prep ===================
__global__ void wprep_kernel(const float* __restrict__ w){
    if (blockIdx.x == 0 && threadIdx.x == 0) g_is64 = 1;
    int i = blockIdx.x*256 + threadIdx.x;        // 64 co * 288 ci-pairs
    if (i < CC*288){
        int co = i / 288;
        int kp = i - co*288;
        int k  = kp*2;
        int tap = k >> 6, ci = k & 63;
        float v0 = w[(co*CC + ci  )*9 + tap];
        float v1 = w[(co*CC + ci+1)*9 + tap];
        u32 hp = cvt_bf16x2(v0, v1);
        float f0 = __uint_as_float(hp << 16);
        float f1 = __uint_as_float(hp & 0xFFFF0000u);
        u32 lp = cvt_bf16x2(v0 - f0, v1 - f1);
        u32 off = co*WROW + tap*128 + ci*2;
        char* img = (char*)g_wimg4;
        *(u32*)(img + off)          = hp;
        *(u32*)(img + WPLANE + off) = lp;
    }
}

// =================== idx dtype probe + canonicalize to int32 ===================
__global__ void idx_probe_kernel(const long long* __restrict__ idx64){
    long long bad = 0;
    for (int i = blockIdx.x*blockDim.x + threadIdx.x; i < IDX_N/2;
         i += gridDim.x*blockDim.x){
        long long v = idx64[i];
        if (v < 0 || v >= HWW) bad = 1;
    }
    if (__syncthreads_or(bad != 0) && threadIdx.x == 0) g_is64 = 0;
}
__global__ void idx_convert_kernel(const void* __restrict__ idx_raw){
    const long long* i64 = (const long long*)idx_raw;
    const int*       i32 = (const int*)idx_raw;
    const int is64 = g_is64;
    for (int i = blockIdx.x*blockDim.x + threadIdx.x; i < IDX_N;
         i += gridDim.x*blockDim.x)
        g_idx[i] = is64 ? (int)i64[i] : i32[i];
}

// =================== main: sync-free persistent HMMA ===================
// 8 warps = 2 groups x 4 warps. Group handles one 128px x 64co tile; warp
// tile = 32px x 64co. A fragments loaded DIRECTLY from gathered global rows
// (mma A-frag layout: V0 m=lane/4,k=(lane%4)*2; V1 m+8; V2 k+8; V3 m+8,k+8).
// B fragments via ldmatrix from the resident smem weight image.
__global__ void __launch_bounds__(NT, 1)
latconv_main(const float* __restrict__ bias, float* __restrict__ out)
{
    extern __shared__ char sm[];
    const u32 smb = smem_u32(sm);
    const int tid  = threadIdx.x;
    const int wid  = tid >> 5;
    const int lane = tid & 31;

    for (int i = tid; i < W_BYTES/16; i += NT) ((uint4*)sm)[i] = g_wimg4[i];
    if (tid < CC) ((float*)(sm + SM_BIAS))[tid] = bias[tid];
    __syncthreads();

    const int gw  = wid >> 2;          // tile group 0/1
    const int wm  = wid & 3;           // 32-px strip within tile
    const int tig = lane & 3;
    const int gr  = lane >> 2;         // 0..7
    const u32 b_co   = (u32)((lane & 7) + ((lane >> 4) & 1) * 8);
    const u32 b_koff = (u32)(((lane >> 3) & 1) * 16);
    const u32 Bb  = smb + b_co*WROW + b_koff;      // hi plane base
    const int cpair = (lane & 3) * 2;

    for (int T = blockIdx.x*2 + gw; T < NTILES; T += 2*GRID_MAIN){
        const int wq = T & 3;
        const int h  = (T >> 2) & (HH-1);
        const int b  = T >> 10;
        const int w0 = wq * 128;
        const size_t brow = (size_t)b * HWW;

        float acc[2][8][4];
        #pragma unroll
        for (int i = 0; i < 2; i++)
            #pragma unroll
            for (int j = 0; j < 8; j++)
                #pragma unroll
                for (int kk = 0; kk < 4; kk++) acc[i][j][kk] = 0.f;

        int dy = 0, dx = 0;
        #pragma unroll 1
        for (int p = 0; p < 9; p++){
            // per-tap gathered row pointers (lane-adjusted by tig)
            const int* __restrict__ idr = g_idx + (3*h + dy)*(3*WW) + dx;
            const u32 *ph0[2], *ph1[2], *pl0[2], *pl1[2];
            #pragma unroll
            for (int mt = 0; mt < 2; mt++){
                const int px = w0 + wm*32 + mt*16 + gr;
                const int g0 = __ldg(&idr[3*px]);
                const int g1 = __ldg(&idr[3*(px+8)]);
                ph0[mt] = g_xh + (brow + (size_t)g0)*32 + tig;
                ph1[mt] = g_xh + (brow + (size_t)g1)*32 + tig;
                pl0[mt] = g_xl + (brow + (size_t)g0)*32 + tig;
                pl1[mt] = g_xl + (brow + (size_t)g1)*32 + tig;
            }
            const u32 Bt  = Bb + (u32)(p*128);
            #pragma unroll
            for (int s = 0; s < 4; s++){
                const int wk = s*8;
                u32 ah[2][4], al[2][4];
                #pragma unroll
                for (int mt = 0; mt < 2; mt++){
                    ah[mt][0] = __ldg(ph0[mt] + wk);
                    ah[mt][1] = __ldg(ph1[mt] + wk);
                    ah[mt][2] = __ldg(ph0[mt] + wk + 4);
                    ah[mt][3] = __ldg(ph1[mt] + wk + 4);
                    al[mt][0] = __ldg(pl0[mt] + wk);
                    al[mt][1] = __ldg(pl1[mt] + wk);
                    al[mt][2] = __ldg(pl0[mt] + wk + 4);
                    al[mt][3] = __ldg(pl1[mt] + wk + 4);
                }
                u32 bh[4][4], bl[4][4];
                #pragma unroll
                for (int g2 = 0; g2 < 4; g2++){
                    LDSM4(bh[g2], Bt + g2*(16*WROW) + s*32);
                    LDSM4(bl[g2], Bt + WPLANE + g2*(16*WROW) + s*32);
                }
                #pragma unroll
                for (int mt = 0; mt < 2; mt++)
                    #pragma unroll
                    for (int g2 = 0; g2 < 4; g2++){
                        MMA_BF16(acc[mt][2*g2  ], ah[mt], bh[g2][0], bh[g2][1]);
                        MMA_BF16(acc[mt][2*g2+1], ah[mt], bh[g2][2], bh[g2][3]);
                        MMA_BF16(acc[mt][2*g2  ], al[mt], bh[g2][0], bh[g2][1]);
                        MMA_BF16(acc[mt][2*g2+1], al[mt], bh[g2][2], bh[g2][3]);
                        MMA_BF16(acc[mt][2*g2  ], ah[mt], bl[g2][0], bl[g2][1]);
                        MMA_BF16(acc[mt][2*g2+1], ah[mt], bl[g2][2], bl[g2][3]);
                    }
            }
            if (++dx == 3){ dx = 0; dy++; }
        }

        // ---- epilogue: D + bias -> out (NCHW) ----
        float* ob = out + (size_t)b*CC*HWW + (size_t)h*WW + w0 + wm*32;
        const float* bs = (const float*)(sm + SM_BIAS);
        #pragma unroll
        for (int mt = 0; mt < 2; mt++){
            const int pxo = mt*16 + gr;
            #pragma unroll
            for (int nt = 0; nt < 8; nt++){
                const int co = nt*8 + cpair;
                const float b0 = bs[co], b1 = bs[co+1];
                ob[(size_t)co*HWW     + pxo    ] = acc[mt][nt][0] + b0;
                ob[(size_t)(co+1)*HWW + pxo    ] = acc[mt][nt][1] + b1;
                ob[(size_t)co*HWW     + pxo + 8] = acc[mt][nt][2] + b0;
                ob[(size_t)(co+1)*HWW + pxo + 8] = acc[mt][nt][3] + b1;
            }
        }
    }
}

// =================== launch ===================
extern "C" void kernel_launch(void* const* d_in, const int* in_sizes, int n_in,
                              void* d_out, int out_size)
{
    const float* x    = (const float*)d_in[0];
    const void*  idx  = d_in[1];
    const float* w    = (const float*)d_in[2];
    const float* bias = (const float*)d_in[3];
    float*       out  = (float*)d_out;

    xprep_kernel<<<dim3(HWW/32, BB), dim3(32,8)>>>(x);
    wprep_kernel<<<(CC*288 + 255)/256, 256>>>(w);
    idx_probe_kernel<<<148, 256>>>((const long long*)idx);
    idx_convert_kernel<<<148, 256>>>(idx);

    cudaFuncSetAttribute(latconv_main,
                         cudaFuncAttributeMaxDynamicSharedMemorySize, SMEM_TOTAL);
    latconv_main<<<GRID_MAIN, NT, SMEM_TOTAL>>>(bias, out);
}

// round 12
// speedup vs baseline: 4.2354x; 1.0942x over previous
#include <cuda_runtime.h>
#include <cuda_fp16.h>
#include <cstdint>

typedef unsigned int u32;

#define BB 4
#define CC 64
#define HH 256
#define WW 512
#define HWW (HH*WW)
#define GRID_MAIN 148
#define NTILES (BB*HH*4)          // tile = 128 consecutive w pixels
#define IDX_N (3*HH*3*WW)
#define NT 256                    // 8 warps: 2 tile-groups x 4 warps

// ---- weight smem image: single fp16 plane, [co][1168B row], row = tap*128 + ci*2
#define WROW   1168
#define WPLANE (64*WROW)          // 74752
#define SM_BIAS WPLANE
#define SMEM_TOTAL (WPLANE + 256)

// ---- global scratch ----
__device__ u32   g_xh[(size_t)BB*HWW*32];   // fp16-hi plane [b][hw][ci-pair words]
__device__ u32   g_xl[(size_t)BB*HWW*32];   // fp16-lo residual plane
__device__ uint4 g_wimg4[WPLANE/16];        // fp16 weight image
__device__ int   g_idx[IDX_N];              // canonical int32 indices
__device__ int   g_is64;

// =================== helpers ===================
__device__ __forceinline__ u32 smem_u32(const void* p){
    u32 a; asm("{ .reg .u64 t; cvta.to.shared.u64 t, %1; cvt.u32.u64 %0, t; }":"=r"(a):"l"(p));
    return a;
}
__device__ __forceinline__ u32 f2h2(float lo, float hi){
    __half2 h = __floats2half2_rn(lo, hi);
    return *(u32*)&h;
}

#define LDSM4(r, addr) \
    asm volatile("ldmatrix.sync.aligned.m8n8.x4.shared.b16 {%0,%1,%2,%3}, [%4];" \
        : "=r"((r)[0]),"=r"((r)[1]),"=r"((r)[2]),"=r"((r)[3]) : "r"(addr))

#define MMA_F16(d, a, b0, b1) \
    asm volatile("mma.sync.aligned.m16n8k16.row.col.f32.f16.f16.f32 " \
        "{%0,%1,%2,%3},{%4,%5,%6,%7},{%8,%9},{%0,%1,%2,%3};" \
        : "+f"((d)[0]),"+f"((d)[1]),"+f"((d)[2]),"+f"((d)[3]) \
        : "r"((a)[0]),"r"((a)[1]),"r"((a)[2]),"r"((a)[3]), "r"(b0),"r"(b1))

// =================== prepass: transpose + fp16 hi/lo split ===================
__global__ void xprep_kernel(const float* __restrict__ x){
    __shared__ float tile[CC][33];
    int b  = blockIdx.y;
    int s0 = blockIdx.x * 32;
    int tx = threadIdx.x, ty = threadIdx.y;     // 32 x 8
    const float* xb = x + (size_t)b*CC*HWW;
    #pragma unroll
    for (int cc = ty; cc < CC; cc += 8)
        tile[cc][tx] = xb[(size_t)cc*HWW + s0 + tx];
    __syncthreads();
    int part = ty >> 2;                          // 0 = hi plane, 1 = lo plane
    u32* plane = part ? g_xl : g_xh;
    #pragma unroll
    for (int i = (ty & 3); i < 32; i += 4){
        float v0 = tile[2*tx][i], v1 = tile[2*tx+1][i];
        u32 outw;
        if (!part){
            outw = f2h2(v0, v1);
        } else {
            __half2 h = __floats2half2_rn(v0, v1);
            outw = f2h2(v0 - __low2float(h), v1 - __high2float(h));
        }
        plane[((size_t)b*HWW + s0 + i)*32 + tx] = outw;
    }
}

// =================== weight prep: single fp16 plane ===================
__global__ void wprep_kernel(const float* __restrict__ w){
    if (blockIdx.x == 0 && threadIdx.x == 0) g_is64 = 1;
    int i = blockIdx.x*256 + threadIdx.x;        // 64 co * 288 ci-pairs
    if (i < CC*288){
        int co = i / 288;
        int kp = i - co*288;
        int k  = kp*2;
        int tap = k >> 6, ci = k & 63;
        float v0 = w[(co*CC + ci  )*9 + tap];
        float v1 = w[(co*CC + ci+1)*9 + tap];
        u32 off = co*WROW + tap*128 + ci*2;
        *(u32*)((char*)g_wimg4 + off) = f2h2(v0, v1);
    }
}

// =================== idx dtype probe (prefix scan) + canonicalize ===================
__global__ void idx_probe_kernel(const long long* __restrict__ idx64){
    long long bad = 0;
    for (int i = blockIdx.x*blockDim.x + threadIdx.x; i < IDX_N/16;
         i += gridDim.x*blockDim.x){
        long long v = idx64[i];
        if (v < 0 || v >= HWW) bad = 1;
    }
    if (__syncthreads_or(bad != 0) && threadIdx.x == 0) g_is64 = 0;
}
__global__ void idx_convert_kernel(const void* __restrict__ idx_raw){
    const long long* i64 = (const long long*)idx_raw;
    const int*       i32 = (const int*)idx_raw;
    const int is64 = g_is64;
    for (int i = blockIdx.x*blockDim.x + threadIdx.x; i < IDX_N;
         i += gridDim.x*blockDim.x)
        g_idx[i] = is64 ? (int)i64[i] : i32[i];
}

// =================== main: sync-free persistent HMMA (fp16 2-product) ===================
// 8 warps = 2 groups x 4 warps; warp tile 32px x 64co. A frags direct-LDG
// from gathered rows; B via ldmatrix from resident smem weight plane.
__global__ void __launch_bounds__(NT, 1)
latconv_main(const float* __restrict__ bias, float* __restrict__ out)
{
    extern __shared__ char sm[];
    const u32 smb = smem_u32(sm);
    const int tid  = threadIdx.x;
    const int wid  = tid >> 5;
    const int lane = tid & 31;

    for (int i = tid; i < WPLANE/16; i += NT) ((uint4*)sm)[i] = g_wimg4[i];
    if (tid < CC) ((float*)(sm + SM_BIAS))[tid] = bias[tid];
    __syncthreads();

    const int gw  = wid >> 2;          // tile group 0/1
    const int wm  = wid & 3;           // 32-px strip within tile
    const int tig = lane & 3;
    const int gr  = lane >> 2;         // 0..7
    const u32 b_co   = (u32)((lane & 7) + ((lane >> 4) & 1) * 8);
    const u32 b_koff = (u32)(((lane >> 3) & 1) * 16);
    const u32 Bb  = smb + b_co*WROW + b_koff;
    const int cpair = (lane & 3) * 2;

    for (int T = blockIdx.x*2 + gw; T < NTILES; T += 2*GRID_MAIN){
        const int wq = T & 3;
        const int h  = (T >> 2) & (HH-1);
        const int b  = T >> 10;
        const int w0 = wq * 128;
        const size_t brow = (size_t)b * HWW;

        // ---- hoist ALL idx loads for this tile (36 values -> regs) ----
        int gidx[9][2][2];                 // [tap][mt][0/1]
        {
            const int* __restrict__ ib = g_idx + (3*h)*(3*WW);
            #pragma unroll
            for (int p = 0; p < 9; p++){
                const int dy = p/3, dx = p - 3*(p/3);
                const int* __restrict__ idr = ib + dy*(3*WW) + dx;
                #pragma unroll
                for (int mt = 0; mt < 2; mt++){
                    const int px = w0 + wm*32 + mt*16 + gr;
                    gidx[p][mt][0] = __ldg(&idr[3*px]);
                    gidx[p][mt][1] = __ldg(&idr[3*(px+8)]);
                }
            }
        }

        float acc[2][8][4];
        #pragma unroll
        for (int i = 0; i < 2; i++)
            #pragma unroll
            for (int j = 0; j < 8; j++)
                #pragma unroll
                for (int kk = 0; kk < 4; kk++) acc[i][j][kk] = 0.f;

        #pragma unroll 1
        for (int p = 0; p < 9; p++){
            const u32 *ph0[2], *ph1[2], *pl0[2], *pl1[2];
            #pragma unroll
            for (int mt = 0; mt < 2; mt++){
                const size_t r0 = brow + (size_t)gidx[p][mt][0];
                const size_t r1 = brow + (size_t)gidx[p][mt][1];
                ph0[mt] = g_xh + r0*32 + tig;
                ph1[mt] = g_xh + r1*32 + tig;
                pl0[mt] = g_xl + r0*32 + tig;
                pl1[mt] = g_xl + r1*32 + tig;
            }
            const u32 Bt = Bb + (u32)(p*128);
            #pragma unroll
            for (int s = 0; s < 4; s++){
                const int wk = s*8;
                u32 ah[2][4], al[2][4];
                #pragma unroll
                for (int mt = 0; mt < 2; mt++){
                    ah[mt][0] = __ldg(ph0[mt] + wk);
                    ah[mt][1] = __ldg(ph1[mt] + wk);
                    ah[mt][2] = __ldg(ph0[mt] + wk + 4);
                    ah[mt][3] = __ldg(ph1[mt] + wk + 4);
                    al[mt][0] = __ldg(pl0[mt] + wk);
                    al[mt][1] = __ldg(pl1[mt] + wk);
                    al[mt][2] = __ldg(pl0[mt] + wk + 4);
                    al[mt][3] = __ldg(pl1[mt] + wk + 4);
                }
                u32 bh[4][4];
                #pragma unroll
                for (int g2 = 0; g2 < 4; g2++)
                    LDSM4(bh[g2], Bt + g2*(16*WROW) + s*32);
                #pragma unroll
                for (int mt = 0; mt < 2; mt++)
                    #pragma unroll
                    for (int g2 = 0; g2 < 4; g2++){
                        MMA_F16(acc[mt][2*g2  ], ah[mt], bh[g2][0], bh[g2][1]);
                        MMA_F16(acc[mt][2*g2+1], ah[mt], bh[g2][2], bh[g2][3]);
                        MMA_F16(acc[mt][2*g2  ], al[mt], bh[g2][0], bh[g2][1]);
                        MMA_F16(acc[mt][2*g2+1], al[mt], bh[g2][2], bh[g2][3]);
                    }
            }
        }

        // ---- epilogue: D + bias -> out (NCHW) ----
        float* ob = out + (size_t)b*CC*HWW + (size_t)h*WW + w0 + wm*32;
        const float* bs = (const float*)(sm + SM_BIAS);
        #pragma unroll
        for (int mt = 0; mt < 2; mt++){
            const int pxo = mt*16 + gr;
            #pragma unroll
            for (int nt = 0; nt < 8; nt++){
                const int co = nt*8 + cpair;
                const float b0 = bs[co], b1 = bs[co+1];
                ob[(size_t)co*HWW     + pxo    ] = acc[mt][nt][0] + b0;
                ob[(size_t)(co+1)*HWW + pxo    ] = acc[mt][nt][1] + b1;
                ob[(size_t)co*HWW     + pxo + 8] = acc[mt][nt][2] + b0;
                ob[(size_t)(co+1)*HWW + pxo + 8] = acc[mt][nt][3] + b1;
            }
        }
    }
}

// =================== launch ===================
extern "C" void kernel_launch(void* const* d_in, const int* in_sizes, int n_in,
                              void* d_out, int out_size)
{
    const float* x    = (const float*)d_in[0];
    const void*  idx  = d_in[1];
    const float* w    = (const float*)d_in[2];
    const float* bias = (const float*)d_in[3];
    float*       out  = (float*)d_out;

    xprep_kernel<<<dim3(HWW/32, BB), dim3(32,8)>>>(x);
    wprep_kernel<<<(CC*288 + 255)/256, 256>>>(w);
    idx_probe_kernel<<<64, 256>>>((const long long*)idx);
    idx_convert_kernel<<<592, 256>>>(idx);

    cudaFuncSetAttribute(latconv_main,
                         cudaFuncAttributeMaxDynamicSharedMemorySize, SMEM_TOTAL);
    latconv_main<<<GRID_MAIN, NT, SMEM_TOTAL>>>(bias, out);
}

// round 15
// speedup vs baseline: 7.2993x; 1.7234x over previous
#include <cuda_runtime.h>
#include <cuda_fp16.h>
#include <cstdint>

typedef unsigned int u32;

#define BB 4
#define CC 64
#define HH 256
#define WW 512
#define HWW (HH*WW)
#define GRID_MAIN 148
#define NTILES (BB*HH*4)          // tile = 128 consecutive w pixels
#define IDX_N (3*HH*3*WW)
#define NT 256                    // 8 warps: 2 tile-groups x 4 warps

// ---- weight smem image: single fp16 plane, [co][1168B row], row = tap*128 + word*4
#define WROW   1168
#define WPLANE (64*WROW)          // 74752
#define SM_BIAS WPLANE
#define SMEM_TOTAL (WPLANE + 256)

// ---- global scratch ----
__device__ u32   g_x[(size_t)BB*HWW*32];    // fp16 plane [b][hw][ci-pair words], 128B rows
__device__ uint4 g_wimg4[WPLANE/16];        // fp16 weight image (k-permuted)
__device__ int   g_idx[IDX_N];              // canonical int32 indices
__device__ int   g_is64;

// =================== helpers ===================
__device__ __forceinline__ u32 smem_u32(const void* p){
    u32 a; asm("{ .reg .u64 t; cvta.to.shared.u64 t, %1; cvt.u32.u64 %0, t; }":"=r"(a):"l"(p));
    return a;
}
__device__ __forceinline__ u32 f2h2(float lo, float hi){
    __half2 h = __floats2half2_rn(lo, hi);
    return *(u32*)&h;
}

#define LDSM4(r, addr) \
    asm volatile("ldmatrix.sync.aligned.m8n8.x4.shared.b16 {%0,%1,%2,%3}, [%4];" \
        : "=r"((r)[0]),"=r"((r)[1]),"=r"((r)[2]),"=r"((r)[3]) : "r"(addr))

#define MMA_F16(d, a, b0, b1) \
    asm volatile("mma.sync.aligned.m16n8k16.row.col.f32.f16.f16.f32 " \
        "{%0,%1,%2,%3},{%4,%5,%6,%7},{%8,%9},{%0,%1,%2,%3};" \
        : "+f"((d)[0]),"+f"((d)[1]),"+f"((d)[2]),"+f"((d)[3]) \
        : "r"((a)[0]),"r"((a)[1]),"r"((a)[2]),"r"((a)[3]), "r"(b0),"r"(b1))

// =================== prepass: transpose + fp16 convert (single plane) ===================
__global__ void xprep_kernel(const float* __restrict__ x){
    __shared__ float tile[CC][33];
    int b  = blockIdx.y;
    int s0 = blockIdx.x * 32;
    int tx = threadIdx.x, ty = threadIdx.y;     // 32 x 8
    const float* xb = x + (size_t)b*CC*HWW;
    #pragma unroll
    for (int cc = ty; cc < CC; cc += 8)
        tile[cc][tx] = xb[(size_t)cc*HWW + s0 + tx];
    __syncthreads();
    #pragma unroll
    for (int i = ty; i < 32; i += 8)
        g_x[((size_t)b*HWW + s0 + i)*32 + tx] = f2h2(tile[2*tx][i], tile[2*tx+1][i]);
}

// =================== weight prep: fp16 plane, k-PERMUTED word layout ===================
// stored word j (0..31) within (co, tap): s=j>>3, m=(j>>2)&1, t=j&3
//   -> holds w[ci0 = 16t + 4s + 2m], w[ci0+1]
// This matches the A-side consumption where lane tig reads words 8*tig+2*s(+1)
// as (V0, V2) of k16-group s.
__global__ void wprep_kernel(const float* __restrict__ w){
    if (blockIdx.x == 0 && threadIdx.x == 0) g_is64 = 1;
    int i = blockIdx.x*256 + threadIdx.x;        // 64 co * 9 taps * 32 words
    if (i < CC*288){
        int co = i / 288;
        int r  = i - co*288;
        int tap = r >> 5, j = r & 31;
        int s = j >> 3, m = (j >> 2) & 1, t = j & 3;
        int ci0 = 16*t + 4*s + 2*m;
        float v0 = w[(co*CC + ci0  )*9 + tap];
        float v1 = w[(co*CC + ci0+1)*9 + tap];
        u32 off = co*WROW + tap*128 + j*4;
        *(u32*)((char*)g_wimg4 + off) = f2h2(v0, v1);
    }
}

// =================== idx dtype probe + canonicalize ===================
__global__ void idx_probe_kernel(const long long* __restrict__ idx64){
    long long bad = 0;
    for (int i = blockIdx.x*blockDim.x + threadIdx.x; i < IDX_N/16;
         i += gridDim.x*blockDim.x){
        long long v = idx64[i];
        if (v < 0 || v >= HWW) bad = 1;
    }
    if (__syncthreads_or(bad != 0) && threadIdx.x == 0) g_is64 = 0;
}
__global__ void idx_convert_kernel(const void* __restrict__ idx_raw){
    const long long* i64 = (const long long*)idx_raw;
    const int*       i32 = (const int*)idx_raw;
    const int is64 = g_is64;
    for (int i = blockIdx.x*blockDim.x + threadIdx.x; i < IDX_N;
         i += gridDim.x*blockDim.x)
        g_idx[i] = is64 ? (int)i64[i] : i32[i];
}

// =================== main: sync-free persistent HMMA (single fp16 plane) ===================
__global__ void __launch_bounds__(NT, 1)
latconv_main(const float* __restrict__ bias, float* __restrict__ out)
{
    extern __shared__ char sm[];
    const u32 smb = smem_u32(sm);
    const int tid  = threadIdx.x;
    const int wid  = tid >> 5;
    const int lane = tid & 31;

    for (int i = tid; i < WPLANE/16; i += NT) ((uint4*)sm)[i] = g_wimg4[i];
    if (tid < CC) ((float*)(sm + SM_BIAS))[tid] = bias[tid];
    __syncthreads();

    const int gw  = wid >> 2;          // tile group 0/1
    const int wm  = wid & 3;           // 32-px strip within tile
    const int tig = lane & 3;
    const int gr  = lane >> 2;         // 0..7
    const u32 b_co   = (u32)((lane & 7) + ((lane >> 4) & 1) * 8);
    const u32 b_koff = (u32)(((lane >> 3) & 1) * 16);
    const u32 Bb  = smb + b_co*WROW + b_koff;
    const int cpair = (lane & 3) * 2;

    for (int T = blockIdx.x*2 + gw; T < NTILES; T += 2*GRID_MAIN){
        const int wq = T & 3;
        const int h  = (T >> 2) & (HH-1);
        const int b  = T >> 10;
        const int w0 = wq * 128;
        const size_t brow = (size_t)b * HWW;

        // ---- hoist ALL idx loads for this tile (36 values -> regs) ----
        int gidx[9][2][2];                 // [tap][mt][0/1]
        {
            const int* __restrict__ ib = g_idx + (3*h)*(3*WW);
            #pragma unroll
            for (int p = 0; p < 9; p++){
                const int dy = p/3, dx = p - 3*(p/3);
                const int* __restrict__ idr = ib + dy*(3*WW) + dx;
                #pragma unroll
                for (int mt = 0; mt < 2; mt++){
                    const int px = w0 + wm*32 + mt*16 + gr;
                    gidx[p][mt][0] = __ldg(&idr[3*px]);
                    gidx[p][mt][1] = __ldg(&idr[3*(px+8)]);
                }
            }
        }

        float acc[2][8][4];
        #pragma unroll
        for (int i = 0; i < 2; i++)
            #pragma unroll
            for (int j = 0; j < 8; j++)
                #pragma unroll
                for (int kk = 0; kk < 4; kk++) acc[i][j][kk] = 0.f;

        #pragma unroll 1
        for (int p = 0; p < 9; p++){
            // per-lane row pointers; each lane owns uint2 slot 4*tig+s
            const uint2 *pa0[2], *pa1[2];
            #pragma unroll
            for (int mt = 0; mt < 2; mt++){
                const size_t r0 = brow + (size_t)gidx[p][mt][0];
                const size_t r1 = brow + (size_t)gidx[p][mt][1];
                pa0[mt] = (const uint2*)(g_x + r0*32) + 4*tig;
                pa1[mt] = (const uint2*)(g_x + r1*32) + 4*tig;
            }
            const u32 Bt = Bb + (u32)(p*128);
            #pragma unroll
            for (int s = 0; s < 4; s++){
                u32 ah[2][4];
                #pragma unroll
                for (int mt = 0; mt < 2; mt++){
                    const uint2 v0 = __ldg(pa0[mt] + s);
                    const uint2 v1 = __ldg(pa1[mt] + s);
                    ah[mt][0] = v0.x; ah[mt][1] = v1.x;
                    ah[mt][2] = v0.y; ah[mt][3] = v1.y;
                }
                u32 bh[4][4];
                #pragma unroll
                for (int g2 = 0; g2 < 4; g2++)
                    LDSM4(bh[g2], Bt + g2*(16*WROW) + s*32);
                #pragma unroll
                for (int mt = 0; mt < 2; mt++)
                    #pragma unroll
                    for (int g2 = 0; g2 < 4; g2++){
                        MMA_F16(acc[mt][2*g2  ], ah[mt], bh[g2][0], bh[g2][1]);
                        MMA_F16(acc[mt][2*g2+1], ah[mt], bh[g2][2], bh[g2][3]);
                    }
            }
        }

        // ---- epilogue: D + bias -> out (NCHW) ----
        float* ob = out + (size_t)b*CC*HWW + (size_t)h*WW + w0 + wm*32;
        const float* bs = (const float*)(sm + SM_BIAS);
        #pragma unroll
        for (int mt = 0; mt < 2; mt++){
            const int pxo = mt*16 + gr;
            #pragma unroll
            for (int nt = 0; nt < 8; nt++){
                const int co = nt*8 + cpair;
                const float b0 = bs[co], b1 = bs[co+1];
                ob[(size_t)co*HWW     + pxo    ] = acc[mt][nt][0] + b0;
                ob[(size_t)(co+1)*HWW + pxo    ] = acc[mt][nt][1] + b1;
                ob[(size_t)co*HWW     + pxo + 8] = acc[mt][nt][2] + b0;
                ob[(size_t)(co+1)*HWW + pxo + 8] = acc[mt][nt][3] + b1;
            }
        }
    }
}

// =================== launch ===================
extern "C" void kernel_launch(void* const* d_in, const int* in_sizes, int n_in,
                              void* d_out, int out_size)
{
    const float* x    = (const float*)d_in[0];
    const void*  idx  = d_in[1];
    const float* w    = (const float*)d_in[2];
    const float* bias = (const float*)d_in[3];
    float*       out  = (float*)d_out;

    xprep_kernel<<<dim3(HWW/32, BB), dim3(32,8)>>>(x);
    wprep_kernel<<<(CC*288 + 255)/256, 256>>>(w);
    idx_probe_kernel<<<64, 256>>>((const long long*)idx);
    idx_convert_kernel<<<592, 256>>>(idx);

    cudaFuncSetAttribute(latconv_main,
                         cudaFuncAttributeMaxDynamicSharedMemorySize, SMEM_TOTAL);
    latconv_main<<<GRID_MAIN, NT, SMEM_TOTAL>>>(bias, out);
}

// round 16
// speedup vs baseline: 8.1476x; 1.1162x over previous
#include <cuda_runtime.h>
#include <cuda_fp16.h>
#include <cstdint>

typedef unsigned int u32;

#define BB 4
#define CC 64
#define HH 256
#define WW 512
#define HWW (HH*WW)
#define GRID_MAIN 148
#define NTILES (BB*HH*4)          // tile = 128 consecutive w pixels
#define IDX_N (3*HH*3*WW)
#define NT 512                    // 16 warps: 4 tile-groups x 4 warps

// ---- weight smem image: single fp16 plane, [co][1168B row], row = tap*128 + word*4
#define WROW   1168
#define WPLANE (64*WROW)          // 74752
#define SM_BIAS WPLANE
#define SMEM_TOTAL (WPLANE + 256)

// ---- global scratch ----
__device__ u32   g_x[(size_t)BB*HWW*32];    // fp16 plane [b][hw][ci-pair words], 128B rows
__device__ uint4 g_wimg4[WPLANE/16];        // fp16 weight image (k-permuted, sector-contiguous)
__device__ int   g_idx[IDX_N];              // canonical int32 indices
__device__ int   g_is64;

// =================== helpers ===================
__device__ __forceinline__ u32 smem_u32(const void* p){
    u32 a; asm("{ .reg .u64 t; cvta.to.shared.u64 t, %1; cvt.u32.u64 %0, t; }":"=r"(a):"l"(p));
    return a;
}
__device__ __forceinline__ u32 f2h2(float lo, float hi){
    __half2 h = __floats2half2_rn(lo, hi);
    return *(u32*)&h;
}

#define LDSM4(r, addr) \
    asm volatile("ldmatrix.sync.aligned.m8n8.x4.shared.b16 {%0,%1,%2,%3}, [%4];" \
        : "=r"((r)[0]),"=r"((r)[1]),"=r"((r)[2]),"=r"((r)[3]) : "r"(addr))

#define MMA_F16(d, a, b0, b1) \
    asm volatile("mma.sync.aligned.m16n8k16.row.col.f32.f16.f16.f32 " \
        "{%0,%1,%2,%3},{%4,%5,%6,%7},{%8,%9},{%0,%1,%2,%3};" \
        : "+f"((d)[0]),"+f"((d)[1]),"+f"((d)[2]),"+f"((d)[3]) \
        : "r"((a)[0]),"r"((a)[1]),"r"((a)[2]),"r"((a)[3]), "r"(b0),"r"(b1))

// =================== prepass: transpose + fp16 convert (single plane) ===================
__global__ void xprep_kernel(const float* __restrict__ x){
    __shared__ float tile[CC][33];
    int b  = blockIdx.y;
    int s0 = blockIdx.x * 32;
    int tx = threadIdx.x, ty = threadIdx.y;     // 32 x 8
    const float* xb = x + (size_t)b*CC*HWW;
    #pragma unroll
    for (int cc = ty; cc < CC; cc += 8)
        tile[cc][tx] = xb[(size_t)cc*HWW + s0 + tx];
    __syncthreads();
    #pragma unroll
    for (int i = ty; i < 32; i += 8)
        g_x[((size_t)b*HWW + s0 + i)*32 + tx] = f2h2(tile[2*tx][i], tile[2*tx+1][i]);
}

// =================== weight prep: fp16 plane, sector-contiguous k-permutation ===================
// A-side consumption: lane tig of k16-group s reads words (8s+2*tig, 8s+2*tig+1)
// holding (V0: k=2tig,2tig+1 ; V2: k=2tig+8,2tig+9), with x elements natural (e=ci).
// => positional (s, k=2t+d)   maps to ci = 16s + 4t + d
//    positional (s, k=8+2t+d) maps to ci = 16s + 4t + 2 + d
// B image at element e_B = 16s + k  => word j holds ci0 = 16(j>>3) + 4(j&3) + ((j&4)?2:0).
__global__ void wprep_kernel(const float* __restrict__ w){
    if (blockIdx.x == 0 && threadIdx.x == 0) g_is64 = 1;
    int i = blockIdx.x*256 + threadIdx.x;        // 64 co * 9 taps * 32 words
    if (i < CC*288){
        int co = i / 288;
        int r  = i - co*288;
        int tap = r >> 5, j = r & 31;
        int ci0 = 16*(j>>3) + 4*(j&3) + ((j&4) ? 2 : 0);
        float v0 = w[(co*CC + ci0  )*9 + tap];
        float v1 = w[(co*CC + ci0+1)*9 + tap];
        u32 off = co*WROW + tap*128 + j*4;
        *(u32*)((char*)g_wimg4 + off) = f2h2(v0, v1);
    }
}

// =================== idx dtype probe + canonicalize ===================
__global__ void idx_probe_kernel(const long long* __restrict__ idx64){
    long long bad = 0;
    for (int i = blockIdx.x*blockDim.x + threadIdx.x; i < IDX_N/16;
         i += gridDim.x*blockDim.x){
        long long v = idx64[i];
        if (v < 0 || v >= HWW) bad = 1;
    }
    if (__syncthreads_or(bad != 0) && threadIdx.x == 0) g_is64 = 0;
}
__global__ void idx_convert_kernel(const void* __restrict__ idx_raw){
    const long long* i64 = (const long long*)idx_raw;
    const int*       i32 = (const int*)idx_raw;
    const int is64 = g_is64;
    for (int i = blockIdx.x*blockDim.x + threadIdx.x; i < IDX_N;
         i += gridDim.x*blockDim.x)
        g_idx[i] = is64 ? (int)i64[i] : i32[i];
}

// =================== main: sync-free persistent HMMA, sector-perfect gather ===================
__global__ void __launch_bounds__(NT, 1)
latconv_main(const float* __restrict__ bias, float* __restrict__ out)
{
    extern __shared__ char sm[];
    const u32 smb = smem_u32(sm);
    const int tid  = threadIdx.x;
    const int wid  = tid >> 5;
    const int lane = tid & 31;

    for (int i = tid; i < WPLANE/16; i += NT) ((uint4*)sm)[i] = g_wimg4[i];
    if (tid < CC) ((float*)(sm + SM_BIAS))[tid] = bias[tid];
    __syncthreads();

    const int gw  = wid >> 2;          // tile group 0..3
    const int wm  = wid & 3;           // 32-px strip within tile
    const int tig = lane & 3;
    const int gr  = lane >> 2;         // 0..7
    const u32 b_co   = (u32)((lane & 7) + ((lane >> 4) & 1) * 8);
    const u32 b_koff = (u32)(((lane >> 3) & 1) * 16);
    const u32 Bb  = smb + b_co*WROW + b_koff;
    const int cpair = (lane & 3) * 2;

    for (int T = blockIdx.x*4 + gw; T < NTILES; T += 4*GRID_MAIN){
        const int wq = T & 3;
        const int h  = (T >> 2) & (HH-1);
        const int b  = T >> 10;
        const int w0 = wq * 128;
        const size_t brow = (size_t)b * HWW;

        // ---- hoist ALL idx loads for this tile (36 values -> regs) ----
        int gidx[9][2][2];                 // [tap][mt][0/1]
        {
            const int* __restrict__ ib = g_idx + (3*h)*(3*WW);
            #pragma unroll
            for (int p = 0; p < 9; p++){
                const int dy = p/3, dx = p - 3*(p/3);
                const int* __restrict__ idr = ib + dy*(3*WW) + dx;
                #pragma unroll
                for (int mt = 0; mt < 2; mt++){
                    const int px = w0 + wm*32 + mt*16 + gr;
                    gidx[p][mt][0] = __ldg(&idr[3*px]);
                    gidx[p][mt][1] = __ldg(&idr[3*(px+8)]);
                }
            }
        }

        float acc[2][8][4];
        #pragma unroll
        for (int i = 0; i < 2; i++)
            #pragma unroll
            for (int j = 0; j < 8; j++)
                #pragma unroll
                for (int kk = 0; kk < 4; kk++) acc[i][j][kk] = 0.f;

        #pragma unroll 1
        for (int p = 0; p < 9; p++){
            // per-lane row pointers; quad (tig 0..3) covers one 32B sector per s
            const uint2 *pa0[2], *pa1[2];
            #pragma unroll
            for (int mt = 0; mt < 2; mt++){
                const size_t r0 = brow + (size_t)gidx[p][mt][0];
                const size_t r1 = brow + (size_t)gidx[p][mt][1];
                pa0[mt] = (const uint2*)(g_x + r0*32) + tig;
                pa1[mt] = (const uint2*)(g_x + r1*32) + tig;
            }
            const u32 Bt = Bb + (u32)(p*128);
            #pragma unroll
            for (int s = 0; s < 4; s++){
                u32 ah[2][4];
                #pragma unroll
                for (int mt = 0; mt < 2; mt++){
                    const uint2 v0 = __ldg(pa0[mt] + 4*s);
                    const uint2 v1 = __ldg(pa1[mt] + 4*s);
                    ah[mt][0] = v0.x; ah[mt][1] = v1.x;
                    ah[mt][2] = v0.y; ah[mt][3] = v1.y;
                }
                u32 bh[4][4];
                #pragma unroll
                for (int g2 = 0; g2 < 4; g2++)
                    LDSM4(bh[g2], Bt + g2*(16*WROW) + s*32);
                #pragma unroll
                for (int mt = 0; mt < 2; mt++)
                    #pragma unroll
                    for (int g2 = 0; g2 < 4; g2++){
                        MMA_F16(acc[mt][2*g2  ], ah[mt], bh[g2][0], bh[g2][1]);
                        MMA_F16(acc[mt][2*g2+1], ah[mt], bh[g2][2], bh[g2][3]);
                    }
            }
        }

        // ---- epilogue: D + bias -> out (NCHW) ----
        float* ob = out + (size_t)b*CC*HWW + (size_t)h*WW + w0 + wm*32;
        const float* bs = (const float*)(sm + SM_BIAS);
        #pragma unroll
        for (int mt = 0; mt < 2; mt++){
            const int pxo = mt*16 + gr;
            #pragma unroll
            for (int nt = 0; nt < 8; nt++){
                const int co = nt*8 + cpair;
                const float b0 = bs[co], b1 = bs[co+1];
                ob[(size_t)co*HWW     + pxo    ] = acc[mt][nt][0] + b0;
                ob[(size_t)(co+1)*HWW + pxo    ] = acc[mt][nt][1] + b1;
                ob[(size_t)co*HWW     + pxo + 8] = acc[mt][nt][2] + b0;
                ob[(size_t)(co+1)*HWW + pxo + 8] = acc[mt][nt][3] + b1;
            }
        }
    }
}

// =================== launch ===================
extern "C" void kernel_launch(void* const* d_in, const int* in_sizes, int n_in,
                              void* d_out, int out_size)
{
    const float* x    = (const float*)d_in[0];
    const void*  idx  = d_in[1];
    const float* w    = (const float*)d_in[2];
    const float* bias = (const float*)d_in[3];
    float*       out  = (float*)d_out;

    xprep_kernel<<<dim3(HWW/32, BB), dim3(32,8)>>>(x);
    wprep_kernel<<<(CC*288 + 255)/256, 256>>>(w);
    idx_probe_kernel<<<64, 256>>>((const long long*)idx);
    idx_convert_kernel<<<592, 256>>>(idx);

    cudaFuncSetAttribute(latconv_main,
                         cudaFuncAttributeMaxDynamicSharedMemorySize, SMEM_TOTAL);
    latconv_main<<<GRID_MAIN, NT, SMEM_TOTAL>>>(bias, out);
}